// round 13
// baseline (speedup 1.0000x reference)
#include <cuda_runtime.h>
#include <cuda_bf16.h>
#include <cstdint>

#define BATCH 4
#define NPTS 8192
#define NSAMP 2048
#define KNN_K 16
#define INDIM 64
#define OUTDIM 128
#define CIN 67

typedef unsigned long long ull;

// ---------------- global coordination state (128B-padded hot words) ----------------
__device__ int g_knn[BATCH * NSAMP * KNN_K];
__device__ volatile int g_progress[BATCH * 32];        // one cache line per batch
__device__ __align__(128) int g_mlpEnq;
__device__ __align__(128) volatile int g_mlpAvail;
__device__ __align__(128) int g_mlpTake;
__device__ __align__(128) int g_mlpQueue[1024];

__global__ void init_kernel() {
    g_mlpEnq = 0;
    g_mlpAvail = 0;
    g_mlpTake = 0;
#pragma unroll
    for (int i = 0; i < BATCH; i++) g_progress[i * 32] = 0;
}

#define BAR_MLP() asm volatile("bar.sync 1, 256;" ::: "memory")
#define BAR_KNN() asm volatile("bar.sync 2, 256;" ::: "memory")

// ---- packed f32x2 helpers (per-lane bit-identical to scalar ops) ----
__device__ __forceinline__ ull f2pk(float lo, float hi) {
    ull r; asm("mov.b64 %0, {%1,%2};" : "=l"(r) : "f"(lo), "f"(hi)); return r;
}
__device__ __forceinline__ void f2up(ull v, float& lo, float& hi) {
    asm("mov.b64 {%0,%1}, %2;" : "=f"(lo), "=f"(hi) : "l"(v));
}
__device__ __forceinline__ ull f2add(ull a, ull b) {
    ull r; asm("add.rn.f32x2 %0, %1, %2;" : "=l"(r) : "l"(a), "l"(b)); return r;
}
__device__ __forceinline__ ull f2mul(ull a, ull b) {
    ull r; asm("mul.rn.f32x2 %0, %1, %2;" : "=l"(r) : "l"(a), "l"(b)); return r;
}
__device__ __forceinline__ ull f2fma(ull a, ull b, ull c) {
    ull r; asm("fma.rn.f32x2 %0, %1, %2, %3;" : "=l"(r) : "l"(a), "l"(b), "l"(c)); return r;
}

// smem layout (floats)
#define OFF_W2 8576
#define OFF_DYN 24960
#define MLP_DYN 30720
#define DYN_FLOATS (OFF_DYN + MLP_DYN)
#define DYN_BYTES (DYN_FLOATS * 4)

__device__ __forceinline__ int spread3(int v) {
    return (v & 1) | ((v & 2) << 2) | ((v & 4) << 4);
}

// ============================================================================
// FPS: 1024 threads, 8 pts/thread, f32x2, payload in shared, tournament max.
// ============================================================================
__device__ void fps_part(float* sm, const float* __restrict__ xyz,
                         float* __restrict__ oxyz, int b, int t) {
    float* sxs = sm;
    float* sys = sxs + NPTS;
    float* szs = sys + NPTS;
    int* sorig = (int*)(szs + NPTS);
    int* spay  = sorig + NPTS;
    int* cellCnt = spay + NPTS;
    int* cellStart = cellCnt + 512;
    unsigned* pv = (unsigned*)(cellStart + 512);
    unsigned* pp = pv + 64;
    float* wred = (float*)(pp + 64);
    int* gpos0 = (int*)(wred + 198);

    const int wid = t >> 5;
    const int lane = t & 31;
    const float* bx = xyz + (size_t)b * NPTS * 3;

    {
        float lx = 3.4e38f, ly = 3.4e38f, lz = 3.4e38f;
        float hx = -3.4e38f, hy = -3.4e38f, hz = -3.4e38f;
        for (int i = t; i < NPTS; i += 1024) {
            float x = bx[3 * i], y = bx[3 * i + 1], z = bx[3 * i + 2];
            lx = fminf(lx, x); hx = fmaxf(hx, x);
            ly = fminf(ly, y); hy = fmaxf(hy, y);
            lz = fminf(lz, z); hz = fmaxf(hz, z);
        }
#pragma unroll
        for (int off = 16; off; off >>= 1) {
            lx = fminf(lx, __shfl_xor_sync(~0u, lx, off));
            ly = fminf(ly, __shfl_xor_sync(~0u, ly, off));
            lz = fminf(lz, __shfl_xor_sync(~0u, lz, off));
            hx = fmaxf(hx, __shfl_xor_sync(~0u, hx, off));
            hy = fmaxf(hy, __shfl_xor_sync(~0u, hy, off));
            hz = fmaxf(hz, __shfl_xor_sync(~0u, hz, off));
        }
        if (lane == 0) {
            wred[wid * 6 + 0] = lx; wred[wid * 6 + 1] = ly; wred[wid * 6 + 2] = lz;
            wred[wid * 6 + 3] = hx; wred[wid * 6 + 4] = hy; wred[wid * 6 + 5] = hz;
        }
        if (t < 512) cellCnt[t] = 0;
    }
    __syncthreads();
    if (t == 0) {
        float lx = wred[0], ly = wred[1], lz = wred[2];
        float hx = wred[3], hy = wred[4], hz = wred[5];
        for (int w = 1; w < 32; w++) {
            lx = fminf(lx, wred[w * 6 + 0]); ly = fminf(ly, wred[w * 6 + 1]);
            lz = fminf(lz, wred[w * 6 + 2]);
            hx = fmaxf(hx, wred[w * 6 + 3]); hy = fmaxf(hy, wred[w * 6 + 4]);
            hz = fmaxf(hz, wred[w * 6 + 5]);
        }
        wred[192] = lx; wred[193] = ly; wred[194] = lz;
        wred[195] = (hx > lx) ? 7.9999f / (hx - lx) : 0.0f;
        wred[196] = (hy > ly) ? 7.9999f / (hy - ly) : 0.0f;
        wred[197] = (hz > lz) ? 7.9999f / (hz - lz) : 0.0f;
    }
    __syncthreads();
    const float lox = wred[192], loy = wred[193], loz = wred[194];
    const float scx = wred[195], scy = wred[196], scz = wred[197];
    for (int i = t; i < NPTS; i += 1024) {
        float x = bx[3 * i], y = bx[3 * i + 1], z = bx[3 * i + 2];
        int qx = (int)((x - lox) * scx); qx = qx < 0 ? 0 : (qx > 7 ? 7 : qx);
        int qy = (int)((y - loy) * scy); qy = qy < 0 ? 0 : (qy > 7 ? 7 : qy);
        int qz = (int)((z - loz) * scz); qz = qz < 0 ? 0 : (qz > 7 ? 7 : qz);
        int ci = (spread3(qx) << 2) | (spread3(qy) << 1) | spread3(qz);
        atomicAdd(&cellCnt[ci], 1);
    }
    __syncthreads();
    if (t < 32) {
        int base = t * 16;
        int loc[16]; int run = 0;
#pragma unroll
        for (int k = 0; k < 16; k++) { loc[k] = run; run += cellCnt[base + k]; }
        int inc = run;
#pragma unroll
        for (int off = 1; off < 32; off <<= 1) {
            int v = __shfl_up_sync(~0u, inc, off);
            if (lane >= off) inc += v;
        }
        int excl = inc - run;
#pragma unroll
        for (int k = 0; k < 16; k++) cellStart[base + k] = excl + loc[k];
    }
    __syncthreads();
    if (t < 512) cellCnt[t] = 0;
    __syncthreads();
    for (int i = t; i < NPTS; i += 1024) {
        float x = bx[3 * i], y = bx[3 * i + 1], z = bx[3 * i + 2];
        int qx = (int)((x - lox) * scx); qx = qx < 0 ? 0 : (qx > 7 ? 7 : qx);
        int qy = (int)((y - loy) * scy); qy = qy < 0 ? 0 : (qy > 7 ? 7 : qy);
        int qz = (int)((z - loz) * scz); qz = qz < 0 ? 0 : (qz > 7 ? 7 : qz);
        int ci = (spread3(qx) << 2) | (spread3(qy) << 1) | spread3(qz);
        int p = cellStart[ci] + atomicAdd(&cellCnt[ci], 1);
        sxs[p] = x; sys[p] = y; szs[p] = z;
        sorig[p] = i;
        spay[p] = (i << 13) | p;
        if (i == 0) *gpos0 = p;
    }
    __syncthreads();

    const int base = t * 8;
    ull px2[4], py2[4], pz2[4];
    float pd[8];
    float blx = 3.4e38f, bly = 3.4e38f, blz = 3.4e38f;
    float bhx = -3.4e38f, bhy = -3.4e38f, bhz = -3.4e38f;
#pragma unroll
    for (int m = 0; m < 4; m++) {
        int p0 = base + 2 * m, p1 = p0 + 1;
        float x0 = sxs[p0], y0 = sys[p0], z0 = szs[p0];
        float x1 = sxs[p1], y1 = sys[p1], z1 = szs[p1];
        px2[m] = f2pk(x0, x1); py2[m] = f2pk(y0, y1); pz2[m] = f2pk(z0, z1);
        pd[2 * m] = 1e10f; pd[2 * m + 1] = 1e10f;
        blx = fminf(blx, fminf(x0, x1)); bhx = fmaxf(bhx, fmaxf(x0, x1));
        bly = fminf(bly, fminf(y0, y1)); bhy = fmaxf(bhy, fmaxf(y0, y1));
        blz = fminf(blz, fminf(z0, z1)); bhz = fmaxf(bhz, fmaxf(z0, z1));
    }
    float hvv = 1e10f;
    int hpp;
    {
        int p = 0x7fffffff;
#pragma unroll
        for (int i = 0; i < 8; i++) p = min(p, spay[base + i]);
        hpp = p;
    }
    __syncthreads();

    float cx, cy, cz;
    {
        int p0 = *gpos0;
        cx = sxs[p0]; cy = sys[p0]; cz = szs[p0];
        if (t == 0) {
            float* o = oxyz + (size_t)b * NSAMP * 3;
            o[0] = cx; o[1] = cy; o[2] = cz;
        }
    }

    int par = 0;
    for (int s = 1; s < NSAMP; s++) {
        const float mcx = -cx, mcy = -cy, mcz = -cz;
        float tx = fmaxf(fmaxf(__fadd_rn(blx, mcx), __fadd_rn(cx, -bhx)), 0.0f);
        float ty = fmaxf(fmaxf(__fadd_rn(bly, mcy), __fadd_rn(cy, -bhy)), 0.0f);
        float tz = fmaxf(fmaxf(__fadd_rn(blz, mcz), __fadd_rn(cz, -bhz)), 0.0f);
        float bnd = __fmul_rn(tx, tx);
        bnd = __fmaf_rn(ty, ty, bnd);
        bnd = __fmaf_rn(tz, tz, bnd);
        bool need = bnd < hvv;
        if (__any_sync(0xffffffffu, need)) {
            const ull ncx = f2pk(mcx, mcx);
            const ull ncy = f2pk(mcy, mcy);
            const ull ncz = f2pk(mcz, mcz);
#pragma unroll
            for (int m = 0; m < 4; m++) {
                ull dx = f2add(px2[m], ncx);
                ull dd = f2mul(dx, dx);
                ull dy = f2add(py2[m], ncy);
                dd = f2fma(dy, dy, dd);
                ull dz = f2add(pz2[m], ncz);
                dd = f2fma(dz, dz, dd);
                float d0, d1;
                f2up(dd, d0, d1);
                pd[2 * m] = fminf(pd[2 * m], d0);
                pd[2 * m + 1] = fminf(pd[2 * m + 1], d1);
            }
            float mv = pd[0];
#pragma unroll
            for (int i = 1; i < 8; i++) mv = fmaxf(mv, pd[i]);
            int p = 0x7fffffff;
#pragma unroll
            for (int i = 0; i < 8; i++)
                p = min(p, (pd[i] == mv) ? spay[base + i] : 0x7fffffff);
            hvv = mv; hpp = p;
        }
        unsigned bmaxv = __float_as_uint(hvv);
        unsigned wv = __reduce_max_sync(0xffffffffu, bmaxv);
        unsigned wp = __reduce_min_sync(0xffffffffu,
                                        (bmaxv == wv) ? (unsigned)hpp : 0x7fffffffu);
        if (lane == 0) { pv[par * 32 + wid] = wv; pp[par * 32 + wid] = wp; }
        __syncthreads();
        unsigned v3 = pv[par * 32 + lane];
        unsigned p3 = pp[par * 32 + lane];
        unsigned gv = __reduce_max_sync(0xffffffffu, v3);
        unsigned gp = __reduce_min_sync(0xffffffffu, (v3 == gv) ? p3 : 0x7fffffffu);
        int pos = (int)(gp & 0x1fffu);
        cx = sxs[pos]; cy = sys[pos]; cz = szs[pos];
        if (t == 0) {
            float* o = oxyz + ((size_t)b * NSAMP + s) * 3;
            o[0] = cx; o[1] = cy; o[2] = cz;
            if ((s & 31) == 31) {
                __threadfence();
                g_progress[b * 32] = s + 1;
            }
        }
        par ^= 1;
    }
    if (t == 0) { __threadfence(); g_progress[b * 32] = NSAMP; }
}

// ============================================================================
// KNN chunk: 64 queries, threads 0-255 active (4/query). Named barrier 2.
// ============================================================================
#define KTS 1024

__device__ void knn_chunk(float* dyn, const float* __restrict__ xyz,
                          const float* __restrict__ qxyz, int b, int q0, int t) {
    if (t >= 256) return;
    float* stx = dyn;
    float* sty = dyn + 1024;
    float* stz = dyn + 2048;
    float* st2 = dyn + 3072;
    float* smd = dyn + 4096;
    int*   smi = (int*)(dyn + 7168);

    const int ql = t >> 2;
    const int par = t & 3;
    const int q = q0 + ql;

    const float* qp = qxyz + ((size_t)b * NSAMP + q) * 3;
    const float qx = qp[0], qy = qp[1], qz = qp[2];
    const float q2 = qx * qx + qy * qy + qz * qz;

    float dk[16];
    int ik[16];
#pragma unroll
    for (int i = 0; i < 16; i++) { dk[i] = 3.4e38f; ik[i] = 0; }

    const float* bx = xyz + (size_t)b * NPTS * 3;
    for (int tile = 0; tile < NPTS / KTS; tile++) {
        BAR_KNN();
        for (int i = t; i < KTS; i += 256) {
            int p = tile * KTS + i;
            float x = bx[p * 3 + 0], y = bx[p * 3 + 1], z = bx[p * 3 + 2];
            stx[i] = x; sty[i] = y; stz[i] = z;
            st2[i] = x * x + y * y + z * z;
        }
        BAR_KNN();
        for (int j = par; j < KTS; j += 4) {
            float dot = qx * stx[j] + qy * sty[j] + qz * stz[j];
            float d = q2 + st2[j] - 2.0f * dot;
            if (d < dk[0]) {
                int idx = tile * KTS + j;
                dk[0] = d; ik[0] = idx;
#pragma unroll
                for (int r = 0; r < 15; r++) {
                    if (dk[r] < dk[r + 1]) {
                        float td = dk[r]; dk[r] = dk[r + 1]; dk[r + 1] = td;
                        int ti = ik[r]; ik[r] = ik[r + 1]; ik[r + 1] = ti;
                    }
                }
            }
        }
    }
    BAR_KNN();

    if (par) {
        int basee = ql * 48 + (par - 1) * 16;
#pragma unroll
        for (int i = 0; i < 16; i++) { smd[basee + i] = dk[i]; smi[basee + i] = ik[i]; }
    }
    BAR_KNN();

    if (par == 0) {
        for (int e = 0; e < 48; e++) {
            float d = smd[ql * 48 + e];
            int idx = smi[ql * 48 + e];
            if (d < dk[0] || (d == dk[0] && idx < ik[0])) {
                dk[0] = d; ik[0] = idx;
#pragma unroll
                for (int r = 0; r < 15; r++) {
                    bool sw = (dk[r] < dk[r + 1]) ||
                              (dk[r] == dk[r + 1] && ik[r] < ik[r + 1]);
                    if (sw) {
                        float td = dk[r]; dk[r] = dk[r + 1]; dk[r + 1] = td;
                        int ti = ik[r]; ik[r] = ik[r + 1]; ik[r + 1] = ti;
                    }
                }
            }
        }
        int* dst = g_knn + (((size_t)b * NSAMP + q) << 4);
#pragma unroll
        for (int i = 0; i < 16; i++) dst[i] = ik[i];
    }
    BAR_KNN();
}

// ============================================================================
// MLP tile: 8 queries (128 rows), 256 active threads, 8x8 register tile
// (proven high-intensity config: 64B LDS per 64 FMA per k). Named barrier 1.
// Weights resident at sm[0..24960); scratch at OFF_DYN (28672 <= 30720 ok).
// ============================================================================
__device__ void mlp_tile(float* sm, const float* __restrict__ xyz,
                         const float* __restrict__ feat,
                         const float* __restrict__ newxyz,
                         const float* __restrict__ b1, const float* __restrict__ b2,
                         const float* __restrict__ lg, const float* __restrict__ lb,
                         float* __restrict__ outf, int b, int q0, int t) {
    if (t >= 256) return;
    float* W1s = sm;
    float* W2s = sm + OFF_W2;
    float* dyn = sm + OFF_DYN;
    float* Gs  = dyn;               // 128 x 68  = 8704
    float* Hs  = dyn + 8704;        // 128 x 132 = 16896
    float* Ps  = dyn + 25600;       // 16 x 128  = 2048
    float* Qs  = dyn + 27648;       // 8 x 128   = 1024

    // gather grouped rows: 2 threads per row
    {
        int r = t >> 1, half = t & 1;
        int qlq = r >> 4, kk = r & 15;
        int q = q0 + qlq;
        int nidx = g_knn[(((size_t)b * NSAMP + q) << 4) + kk];
        const float* frow = feat + ((size_t)b * NPTS + nidx) * INDIM + half * 32;
        float* grow = Gs + r * 68;
#pragma unroll
        for (int i = 0; i < 8; i++) {
            float4 v = *(const float4*)(frow + i * 4);
            *(float4*)(grow + half * 32 + i * 4) = v;
        }
        if (half == 0) {
            const float* prow = xyz + ((size_t)b * NPTS + nidx) * 3;
            const float* crow = newxyz + ((size_t)b * NSAMP + q) * 3;
            grow[64] = prow[0] - crow[0];
            grow[65] = prow[1] - crow[1];
            grow[66] = prow[2] - crow[2];
        }
    }
    BAR_MLP();

    const int tx = t & 15, ty = t >> 4;
    const int c0 = tx * 8, r0 = ty * 8;

    float acc[8][8];
    {
        float bb[8];
#pragma unroll
        for (int j = 0; j < 8; j++) bb[j] = __ldg(b1 + c0 + j);
#pragma unroll
        for (int i = 0; i < 8; i++)
#pragma unroll
            for (int j = 0; j < 8; j++) acc[i][j] = bb[j];
    }
    for (int k = 0; k < CIN; k++) {
        float w[8], g[8];
        float4 w0 = *(const float4*)(W1s + k * 128 + c0);
        float4 w1 = *(const float4*)(W1s + k * 128 + c0 + 4);
        w[0] = w0.x; w[1] = w0.y; w[2] = w0.z; w[3] = w0.w;
        w[4] = w1.x; w[5] = w1.y; w[6] = w1.z; w[7] = w1.w;
#pragma unroll
        for (int i = 0; i < 8; i++) g[i] = Gs[(r0 + i) * 68 + k];
#pragma unroll
        for (int i = 0; i < 8; i++)
#pragma unroll
            for (int j = 0; j < 8; j++) acc[i][j] += g[i] * w[j];
    }
#pragma unroll
    for (int i = 0; i < 8; i++) {
        float4 v0, v1;
        v0.x = fmaxf(acc[i][0], 0.f); v0.y = fmaxf(acc[i][1], 0.f);
        v0.z = fmaxf(acc[i][2], 0.f); v0.w = fmaxf(acc[i][3], 0.f);
        v1.x = fmaxf(acc[i][4], 0.f); v1.y = fmaxf(acc[i][5], 0.f);
        v1.z = fmaxf(acc[i][6], 0.f); v1.w = fmaxf(acc[i][7], 0.f);
        *(float4*)(Hs + (r0 + i) * 132 + c0) = v0;
        *(float4*)(Hs + (r0 + i) * 132 + c0 + 4) = v1;
    }
    BAR_MLP();

    {
        float bb[8];
#pragma unroll
        for (int j = 0; j < 8; j++) bb[j] = __ldg(b2 + c0 + j);
#pragma unroll
        for (int i = 0; i < 8; i++)
#pragma unroll
            for (int j = 0; j < 8; j++) acc[i][j] = bb[j];
    }
    for (int k = 0; k < OUTDIM; k++) {
        float w[8], h[8];
        float4 w0 = *(const float4*)(W2s + k * 128 + c0);
        float4 w1 = *(const float4*)(W2s + k * 128 + c0 + 4);
        w[0] = w0.x; w[1] = w0.y; w[2] = w0.z; w[3] = w0.w;
        w[4] = w1.x; w[5] = w1.y; w[6] = w1.z; w[7] = w1.w;
#pragma unroll
        for (int i = 0; i < 8; i++) h[i] = Hs[(r0 + i) * 132 + k];
#pragma unroll
        for (int i = 0; i < 8; i++)
#pragma unroll
            for (int j = 0; j < 8; j++) acc[i][j] += h[i] * w[j];
    }
    {
        float m[8];
#pragma unroll
        for (int j = 0; j < 8; j++) {
            float v = acc[0][j];
#pragma unroll
            for (int i = 1; i < 8; i++) v = fmaxf(v, acc[i][j]);
            m[j] = v;
        }
        float4 v0, v1;
        v0.x = m[0]; v0.y = m[1]; v0.z = m[2]; v0.w = m[3];
        v1.x = m[4]; v1.y = m[5]; v1.z = m[6]; v1.w = m[7];
        *(float4*)(Ps + ty * 128 + c0) = v0;
        *(float4*)(Ps + ty * 128 + c0 + 4) = v1;
    }
    BAR_MLP();
    for (int e = t; e < 1024; e += 256) {
        int q = e >> 7, c = e & 127;
        Qs[e] = fmaxf(Ps[(2 * q) * 128 + c], Ps[(2 * q + 1) * 128 + c]);
    }
    BAR_MLP();

    {
        int w = t >> 5, l = t & 31;
        float4 v = *(const float4*)(Qs + w * 128 + l * 4);
        float sum = v.x + v.y + v.z + v.w;
        float sq = fmaf(v.x, v.x, fmaf(v.y, v.y, fmaf(v.z, v.z, v.w * v.w)));
#pragma unroll
        for (int off = 16; off; off >>= 1) {
            sum += __shfl_xor_sync(0xffffffffu, sum, off);
            sq += __shfl_xor_sync(0xffffffffu, sq, off);
        }
        float mu = sum * (1.0f / 128.0f);
        float var = sq * (1.0f / 128.0f) - mu * mu;
        float rs = rsqrtf(var + 1e-5f);
        int qg = q0 + w;
        int c = l * 4;
        float4 o;
        o.x = (v.x - mu) * rs * __ldg(lg + c + 0) + __ldg(lb + c + 0);
        o.y = (v.y - mu) * rs * __ldg(lg + c + 1) + __ldg(lb + c + 1);
        o.z = (v.z - mu) * rs * __ldg(lg + c + 2) + __ldg(lb + c + 2);
        o.w = (v.w - mu) * rs * __ldg(lg + c + 3) + __ldg(lb + c + 3);
        *(float4*)(outf + (((size_t)b * NSAMP + qg) << 7) + c) = o;
    }
    BAR_MLP();
}

__device__ void load_weights(float* sm, const float* __restrict__ W1,
                             const float* __restrict__ W2, int t) {
    for (int e = t; e < CIN * OUTDIM; e += 1024) {
        int sr = e >> 7, c = e & 127;
        int dr = (sr < 3) ? (64 + sr) : (sr - 3);
        sm[dr * 128 + c] = W1[e];
    }
    const float4* src = (const float4*)W2;
    float4* dst = (float4*)(sm + OFF_W2);
    for (int e = t; e < 4096; e += 1024) dst[e] = src[e];
}

// ============================================================================
// Fused persistent kernel with ready-queue scheduler.
// ============================================================================
__global__ __launch_bounds__(1024, 1)
void fused_kernel(const float* __restrict__ xyz, const float* __restrict__ feat,
                  const float* __restrict__ W1, const float* __restrict__ b1,
                  const float* __restrict__ W2, const float* __restrict__ b2,
                  const float* __restrict__ lg, const float* __restrict__ lb,
                  float* __restrict__ oxyz, float* __restrict__ ofeat) {
    extern __shared__ float sm[];
    __shared__ int shA, shQ0, shB;
    const int t = threadIdx.x;
    const int bid = blockIdx.x;

    int pendChunk = -1, pendB = 0, pendNeed = 0;

    if (bid < BATCH) {
        fps_part(sm, xyz, oxyz, bid, t);
        __syncthreads();
        load_weights(sm, W1, W2, t);
        __syncthreads();
    } else {
        int w = bid - BATCH;             // 0..143
        if (w < 128) {
            pendChunk = w >> 2;          // 0..31
            pendB = w & 3;
            pendNeed = (pendChunk + 1) * 64;
        }
        load_weights(sm, W1, W2, t);
        __syncthreads();
    }

    while (true) {
        __syncthreads();
        if (t == 0) {
            int a, q0 = 0, bb = 0;
            bool hasPend = (pendChunk >= 0);
            while (true) {
                if (hasPend && g_progress[pendB * 32] >= pendNeed) { a = 1; break; }
                if (hasPend) {
                    int cur = g_mlpTake;
                    if (cur < g_mlpAvail && cur < 1024) {
                        if (atomicCAS(&g_mlpTake, cur, cur + 1) == cur) {
                            __threadfence();
                            int m = g_mlpQueue[cur];
                            a = 2; q0 = (m >> 5) * 64 + (m & 7) * 8; bb = (m >> 3) & 3;
                            break;
                        }
                    } else {
                        __nanosleep(1000);
                    }
                } else {
                    int tk = atomicAdd(&g_mlpTake, 1);
                    if (tk >= 1024) { a = 0; break; }
                    while (g_mlpAvail <= tk) __nanosleep(500);
                    __threadfence();
                    int m = g_mlpQueue[tk];
                    a = 2; q0 = (m >> 5) * 64 + (m & 7) * 8; bb = (m >> 3) & 3;
                    break;
                }
            }
            shA = a; shQ0 = q0; shB = bb;
        }
        __syncthreads();
        int a = shA;
        if (a == 0) break;

        if (a == 1) {
            knn_chunk(sm + OFF_DYN, xyz, oxyz, pendB, pendChunk * 64, t);
            __syncthreads();
            if (t == 0) {
                int fi = pendChunk * 4 + pendB;
                int pos = atomicAdd(&g_mlpEnq, 8);
#pragma unroll
                for (int j = 0; j < 8; j++) g_mlpQueue[pos + j] = fi * 8 + j;
                __threadfence();
                while (g_mlpAvail != pos) __nanosleep(100);
                g_mlpAvail = pos + 8;
            }
            pendChunk = -1;
        } else {
            mlp_tile(sm, xyz, feat, oxyz, b1, b2, lg, lb, ofeat, shB, shQ0, t);
        }
    }
}

// ============================================================================
extern "C" void kernel_launch(void* const* d_in, const int* in_sizes, int n_in,
                              void* d_out, int out_size) {
    const float* xyz  = (const float*)d_in[0];
    const float* feat = (const float*)d_in[1];
    const float* W1   = (const float*)d_in[2];
    const float* b1   = (const float*)d_in[3];
    const float* W2   = (const float*)d_in[4];
    const float* b2   = (const float*)d_in[5];
    const float* lg   = (const float*)d_in[6];
    const float* lb   = (const float*)d_in[7];

    float* out = (float*)d_out;
    float* oxyz = out;                                  // (B, S, 3)
    float* ofeat = out + (size_t)BATCH * NSAMP * 3;     // (B, S, 128)

    cudaFuncSetAttribute(fused_kernel, cudaFuncAttributeMaxDynamicSharedMemorySize, DYN_BYTES);

    init_kernel<<<1, 1>>>();
    fused_kernel<<<148, 1024, DYN_BYTES>>>(xyz, feat, W1, b1, W2, b2, lg, lb, oxyz, ofeat);
}

// round 14
// speedup vs baseline: 1.3188x; 1.3188x over previous
#include <cuda_runtime.h>
#include <cuda_bf16.h>
#include <cstdint>

#define BATCH 4
#define NPTS 8192
#define NSAMP 2048
#define KNN_K 16
#define INDIM 64
#define OUTDIM 128
#define CIN 67

typedef unsigned long long ull;

// ---------------- global coordination state (128B-padded hot words) ----------------
__device__ int g_knn[BATCH * NSAMP * KNN_K];
__device__ volatile int g_progress[BATCH * 32];
__device__ __align__(128) int g_mlpEnq;
__device__ __align__(128) volatile int g_mlpAvail;
__device__ __align__(128) int g_mlpTake;
__device__ __align__(128) int g_mlpQueue[1024];

__global__ void init_kernel() {
    g_mlpEnq = 0;
    g_mlpAvail = 0;
    g_mlpTake = 0;
#pragma unroll
    for (int i = 0; i < BATCH; i++) g_progress[i * 32] = 0;
}

#define BAR_MLP() asm volatile("bar.sync 1, 512;" ::: "memory")
#define BAR_KNN() asm volatile("bar.sync 2, 256;" ::: "memory")

// ---- packed f32x2 helpers (per-lane bit-identical to scalar ops) ----
__device__ __forceinline__ ull f2pk(float lo, float hi) {
    ull r; asm("mov.b64 %0, {%1,%2};" : "=l"(r) : "f"(lo), "f"(hi)); return r;
}
__device__ __forceinline__ void f2up(ull v, float& lo, float& hi) {
    asm("mov.b64 {%0,%1}, %2;" : "=f"(lo), "=f"(hi) : "l"(v));
}
__device__ __forceinline__ ull f2add(ull a, ull b) {
    ull r; asm("add.rn.f32x2 %0, %1, %2;" : "=l"(r) : "l"(a), "l"(b)); return r;
}
__device__ __forceinline__ ull f2mul(ull a, ull b) {
    ull r; asm("mul.rn.f32x2 %0, %1, %2;" : "=l"(r) : "l"(a), "l"(b)); return r;
}
__device__ __forceinline__ ull f2fma(ull a, ull b, ull c) {
    ull r; asm("fma.rn.f32x2 %0, %1, %2, %3;" : "=l"(r) : "l"(a), "l"(b), "l"(c)); return r;
}

// smem layout (floats)
#define OFF_W2 8576
#define OFF_DYN 24960
#define MLP_DYN 30720
#define DYN_FLOATS (OFF_DYN + MLP_DYN)
#define DYN_BYTES (DYN_FLOATS * 4)

__device__ __forceinline__ int spread3(int v) {
    return (v & 1) | ((v & 2) << 2) | ((v & 4) << 4);
}

// ============================================================================
// FPS: 1024 threads, 8 pts/thread, f32x2, payload in shared, tournament max.
// ============================================================================
__device__ void fps_part(float* sm, const float* __restrict__ xyz,
                         float* __restrict__ oxyz, int b, int t) {
    float* sxs = sm;
    float* sys = sxs + NPTS;
    float* szs = sys + NPTS;
    int* sorig = (int*)(szs + NPTS);
    int* spay  = sorig + NPTS;
    int* cellCnt = spay + NPTS;
    int* cellStart = cellCnt + 512;
    unsigned* pv = (unsigned*)(cellStart + 512);
    unsigned* pp = pv + 64;
    float* wred = (float*)(pp + 64);
    int* gpos0 = (int*)(wred + 198);

    const int wid = t >> 5;
    const int lane = t & 31;
    const float* bx = xyz + (size_t)b * NPTS * 3;

    {
        float lx = 3.4e38f, ly = 3.4e38f, lz = 3.4e38f;
        float hx = -3.4e38f, hy = -3.4e38f, hz = -3.4e38f;
        for (int i = t; i < NPTS; i += 1024) {
            float x = bx[3 * i], y = bx[3 * i + 1], z = bx[3 * i + 2];
            lx = fminf(lx, x); hx = fmaxf(hx, x);
            ly = fminf(ly, y); hy = fmaxf(hy, y);
            lz = fminf(lz, z); hz = fmaxf(hz, z);
        }
#pragma unroll
        for (int off = 16; off; off >>= 1) {
            lx = fminf(lx, __shfl_xor_sync(~0u, lx, off));
            ly = fminf(ly, __shfl_xor_sync(~0u, ly, off));
            lz = fminf(lz, __shfl_xor_sync(~0u, lz, off));
            hx = fmaxf(hx, __shfl_xor_sync(~0u, hx, off));
            hy = fmaxf(hy, __shfl_xor_sync(~0u, hy, off));
            hz = fmaxf(hz, __shfl_xor_sync(~0u, hz, off));
        }
        if (lane == 0) {
            wred[wid * 6 + 0] = lx; wred[wid * 6 + 1] = ly; wred[wid * 6 + 2] = lz;
            wred[wid * 6 + 3] = hx; wred[wid * 6 + 4] = hy; wred[wid * 6 + 5] = hz;
        }
        if (t < 512) cellCnt[t] = 0;
    }
    __syncthreads();
    if (t == 0) {
        float lx = wred[0], ly = wred[1], lz = wred[2];
        float hx = wred[3], hy = wred[4], hz = wred[5];
        for (int w = 1; w < 32; w++) {
            lx = fminf(lx, wred[w * 6 + 0]); ly = fminf(ly, wred[w * 6 + 1]);
            lz = fminf(lz, wred[w * 6 + 2]);
            hx = fmaxf(hx, wred[w * 6 + 3]); hy = fmaxf(hy, wred[w * 6 + 4]);
            hz = fmaxf(hz, wred[w * 6 + 5]);
        }
        wred[192] = lx; wred[193] = ly; wred[194] = lz;
        wred[195] = (hx > lx) ? 7.9999f / (hx - lx) : 0.0f;
        wred[196] = (hy > ly) ? 7.9999f / (hy - ly) : 0.0f;
        wred[197] = (hz > lz) ? 7.9999f / (hz - lz) : 0.0f;
    }
    __syncthreads();
    const float lox = wred[192], loy = wred[193], loz = wred[194];
    const float scx = wred[195], scy = wred[196], scz = wred[197];
    for (int i = t; i < NPTS; i += 1024) {
        float x = bx[3 * i], y = bx[3 * i + 1], z = bx[3 * i + 2];
        int qx = (int)((x - lox) * scx); qx = qx < 0 ? 0 : (qx > 7 ? 7 : qx);
        int qy = (int)((y - loy) * scy); qy = qy < 0 ? 0 : (qy > 7 ? 7 : qy);
        int qz = (int)((z - loz) * scz); qz = qz < 0 ? 0 : (qz > 7 ? 7 : qz);
        int ci = (spread3(qx) << 2) | (spread3(qy) << 1) | spread3(qz);
        atomicAdd(&cellCnt[ci], 1);
    }
    __syncthreads();
    if (t < 32) {
        int base = t * 16;
        int loc[16]; int run = 0;
#pragma unroll
        for (int k = 0; k < 16; k++) { loc[k] = run; run += cellCnt[base + k]; }
        int inc = run;
#pragma unroll
        for (int off = 1; off < 32; off <<= 1) {
            int v = __shfl_up_sync(~0u, inc, off);
            if (lane >= off) inc += v;
        }
        int excl = inc - run;
#pragma unroll
        for (int k = 0; k < 16; k++) cellStart[base + k] = excl + loc[k];
    }
    __syncthreads();
    if (t < 512) cellCnt[t] = 0;
    __syncthreads();
    for (int i = t; i < NPTS; i += 1024) {
        float x = bx[3 * i], y = bx[3 * i + 1], z = bx[3 * i + 2];
        int qx = (int)((x - lox) * scx); qx = qx < 0 ? 0 : (qx > 7 ? 7 : qx);
        int qy = (int)((y - loy) * scy); qy = qy < 0 ? 0 : (qy > 7 ? 7 : qy);
        int qz = (int)((z - loz) * scz); qz = qz < 0 ? 0 : (qz > 7 ? 7 : qz);
        int ci = (spread3(qx) << 2) | (spread3(qy) << 1) | spread3(qz);
        int p = cellStart[ci] + atomicAdd(&cellCnt[ci], 1);
        sxs[p] = x; sys[p] = y; szs[p] = z;
        sorig[p] = i;
        spay[p] = (i << 13) | p;
        if (i == 0) *gpos0 = p;
    }
    __syncthreads();

    const int base = t * 8;
    ull px2[4], py2[4], pz2[4];
    float pd[8];
    float blx = 3.4e38f, bly = 3.4e38f, blz = 3.4e38f;
    float bhx = -3.4e38f, bhy = -3.4e38f, bhz = -3.4e38f;
#pragma unroll
    for (int m = 0; m < 4; m++) {
        int p0 = base + 2 * m, p1 = p0 + 1;
        float x0 = sxs[p0], y0 = sys[p0], z0 = szs[p0];
        float x1 = sxs[p1], y1 = sys[p1], z1 = szs[p1];
        px2[m] = f2pk(x0, x1); py2[m] = f2pk(y0, y1); pz2[m] = f2pk(z0, z1);
        pd[2 * m] = 1e10f; pd[2 * m + 1] = 1e10f;
        blx = fminf(blx, fminf(x0, x1)); bhx = fmaxf(bhx, fmaxf(x0, x1));
        bly = fminf(bly, fminf(y0, y1)); bhy = fmaxf(bhy, fmaxf(y0, y1));
        blz = fminf(blz, fminf(z0, z1)); bhz = fmaxf(bhz, fmaxf(z0, z1));
    }
    float hvv = 1e10f;
    int hpp;
    {
        int p = 0x7fffffff;
#pragma unroll
        for (int i = 0; i < 8; i++) p = min(p, spay[base + i]);
        hpp = p;
    }
    __syncthreads();

    float cx, cy, cz;
    {
        int p0 = *gpos0;
        cx = sxs[p0]; cy = sys[p0]; cz = szs[p0];
        if (t == 0) {
            float* o = oxyz + (size_t)b * NSAMP * 3;
            o[0] = cx; o[1] = cy; o[2] = cz;
        }
    }

    int par = 0;
    for (int s = 1; s < NSAMP; s++) {
        const float mcx = -cx, mcy = -cy, mcz = -cz;
        float tx = fmaxf(fmaxf(__fadd_rn(blx, mcx), __fadd_rn(cx, -bhx)), 0.0f);
        float ty = fmaxf(fmaxf(__fadd_rn(bly, mcy), __fadd_rn(cy, -bhy)), 0.0f);
        float tz = fmaxf(fmaxf(__fadd_rn(blz, mcz), __fadd_rn(cz, -bhz)), 0.0f);
        float bnd = __fmul_rn(tx, tx);
        bnd = __fmaf_rn(ty, ty, bnd);
        bnd = __fmaf_rn(tz, tz, bnd);
        bool need = bnd < hvv;
        if (__any_sync(0xffffffffu, need)) {
            const ull ncx = f2pk(mcx, mcx);
            const ull ncy = f2pk(mcy, mcy);
            const ull ncz = f2pk(mcz, mcz);
#pragma unroll
            for (int m = 0; m < 4; m++) {
                ull dx = f2add(px2[m], ncx);
                ull dd = f2mul(dx, dx);
                ull dy = f2add(py2[m], ncy);
                dd = f2fma(dy, dy, dd);
                ull dz = f2add(pz2[m], ncz);
                dd = f2fma(dz, dz, dd);
                float d0, d1;
                f2up(dd, d0, d1);
                pd[2 * m] = fminf(pd[2 * m], d0);
                pd[2 * m + 1] = fminf(pd[2 * m + 1], d1);
            }
            float mv = pd[0];
#pragma unroll
            for (int i = 1; i < 8; i++) mv = fmaxf(mv, pd[i]);
            int p = 0x7fffffff;
#pragma unroll
            for (int i = 0; i < 8; i++)
                p = min(p, (pd[i] == mv) ? spay[base + i] : 0x7fffffff);
            hvv = mv; hpp = p;
        }
        unsigned bmaxv = __float_as_uint(hvv);
        unsigned wv = __reduce_max_sync(0xffffffffu, bmaxv);
        unsigned wp = __reduce_min_sync(0xffffffffu,
                                        (bmaxv == wv) ? (unsigned)hpp : 0x7fffffffu);
        if (lane == 0) { pv[par * 32 + wid] = wv; pp[par * 32 + wid] = wp; }
        __syncthreads();
        unsigned v3 = pv[par * 32 + lane];
        unsigned p3 = pp[par * 32 + lane];
        unsigned gv = __reduce_max_sync(0xffffffffu, v3);
        unsigned gp = __reduce_min_sync(0xffffffffu, (v3 == gv) ? p3 : 0x7fffffffu);
        int pos = (int)(gp & 0x1fffu);
        cx = sxs[pos]; cy = sys[pos]; cz = szs[pos];
        if (t == 0) {
            float* o = oxyz + ((size_t)b * NSAMP + s) * 3;
            o[0] = cx; o[1] = cy; o[2] = cz;
            if ((s & 31) == 31) {
                __threadfence();
                g_progress[b * 32] = s + 1;
            }
        }
        par ^= 1;
    }
    if (t == 0) { __threadfence(); g_progress[b * 32] = NSAMP; }
}

// ============================================================================
// KNN chunk: 64 queries, threads 0-255 active (4/query). Named barrier 2.
// ============================================================================
#define KTS 1024

__device__ void knn_chunk(float* dyn, const float* __restrict__ xyz,
                          const float* __restrict__ qxyz, int b, int q0, int t) {
    if (t >= 256) return;
    float* stx = dyn;
    float* sty = dyn + 1024;
    float* stz = dyn + 2048;
    float* st2 = dyn + 3072;
    float* smd = dyn + 4096;
    int*   smi = (int*)(dyn + 7168);

    const int ql = t >> 2;
    const int par = t & 3;
    const int q = q0 + ql;

    const float* qp = qxyz + ((size_t)b * NSAMP + q) * 3;
    const float qx = qp[0], qy = qp[1], qz = qp[2];
    const float q2 = qx * qx + qy * qy + qz * qz;

    float dk[16];
    int ik[16];
#pragma unroll
    for (int i = 0; i < 16; i++) { dk[i] = 3.4e38f; ik[i] = 0; }

    const float* bx = xyz + (size_t)b * NPTS * 3;
    for (int tile = 0; tile < NPTS / KTS; tile++) {
        BAR_KNN();
        for (int i = t; i < KTS; i += 256) {
            int p = tile * KTS + i;
            float x = bx[p * 3 + 0], y = bx[p * 3 + 1], z = bx[p * 3 + 2];
            stx[i] = x; sty[i] = y; stz[i] = z;
            st2[i] = x * x + y * y + z * z;
        }
        BAR_KNN();
        for (int j = par; j < KTS; j += 4) {
            float dot = qx * stx[j] + qy * sty[j] + qz * stz[j];
            float d = q2 + st2[j] - 2.0f * dot;
            if (d < dk[0]) {
                int idx = tile * KTS + j;
                dk[0] = d; ik[0] = idx;
#pragma unroll
                for (int r = 0; r < 15; r++) {
                    if (dk[r] < dk[r + 1]) {
                        float td = dk[r]; dk[r] = dk[r + 1]; dk[r + 1] = td;
                        int ti = ik[r]; ik[r] = ik[r + 1]; ik[r + 1] = ti;
                    }
                }
            }
        }
    }
    BAR_KNN();

    if (par) {
        int basee = ql * 48 + (par - 1) * 16;
#pragma unroll
        for (int i = 0; i < 16; i++) { smd[basee + i] = dk[i]; smi[basee + i] = ik[i]; }
    }
    BAR_KNN();

    if (par == 0) {
        for (int e = 0; e < 48; e++) {
            float d = smd[ql * 48 + e];
            int idx = smi[ql * 48 + e];
            if (d < dk[0] || (d == dk[0] && idx < ik[0])) {
                dk[0] = d; ik[0] = idx;
#pragma unroll
                for (int r = 0; r < 15; r++) {
                    bool sw = (dk[r] < dk[r + 1]) ||
                              (dk[r] == dk[r + 1] && ik[r] < ik[r + 1]);
                    if (sw) {
                        float td = dk[r]; dk[r] = dk[r + 1]; dk[r + 1] = td;
                        int ti = ik[r]; ik[r] = ik[r + 1]; ik[r + 1] = ti;
                    }
                }
            }
        }
        int* dst = g_knn + (((size_t)b * NSAMP + q) << 4);
#pragma unroll
        for (int i = 0; i < 16; i++) dst[i] = ik[i];
    }
    BAR_KNN();
}

// ============================================================================
// MLP tile: 8 queries (128 rows), 512 active threads, 4x8 register tile
// (~55 regs, fits the 64-reg cap; 48B LDS per 32 FMA per k). Named barrier 1.
// Scratch: Gs 8704 + Hs 16896 + Ps 4096 + Qs 1024 = 30720 = MLP_DYN.
// ============================================================================
__device__ void mlp_tile(float* sm, const float* __restrict__ xyz,
                         const float* __restrict__ feat,
                         const float* __restrict__ newxyz,
                         const float* __restrict__ b1, const float* __restrict__ b2,
                         const float* __restrict__ lg, const float* __restrict__ lb,
                         float* __restrict__ outf, int b, int q0, int t) {
    if (t >= 512) return;
    float* W1s = sm;
    float* W2s = sm + OFF_W2;
    float* dyn = sm + OFF_DYN;
    float* Gs  = dyn;               // 128 x 68  = 8704
    float* Hs  = dyn + 8704;        // 128 x 132 = 16896
    float* Ps  = dyn + 25600;       // 32 x 128  = 4096
    float* Qs  = dyn + 29696;       // 8 x 128   = 1024

    // gather grouped rows: 4 threads per row (16 floats each)
    {
        int r = t >> 2, quar = t & 3;
        int qlq = r >> 4, kk = r & 15;
        int q = q0 + qlq;
        int nidx = g_knn[(((size_t)b * NSAMP + q) << 4) + kk];
        const float* frow = feat + ((size_t)b * NPTS + nidx) * INDIM + quar * 16;
        float* grow = Gs + r * 68;
#pragma unroll
        for (int i = 0; i < 4; i++) {
            float4 v = *(const float4*)(frow + i * 4);
            *(float4*)(grow + quar * 16 + i * 4) = v;
        }
        if (quar == 0) {
            const float* prow = xyz + ((size_t)b * NPTS + nidx) * 3;
            const float* crow = newxyz + ((size_t)b * NSAMP + q) * 3;
            grow[64] = prow[0] - crow[0];
            grow[65] = prow[1] - crow[1];
            grow[66] = prow[2] - crow[2];
        }
    }
    BAR_MLP();

    const int tx = t & 15, ty = t >> 4;   // ty 0..31
    const int c0 = tx * 8, r0 = ty * 4;

    float acc[4][8];
    {
        float bb[8];
#pragma unroll
        for (int j = 0; j < 8; j++) bb[j] = __ldg(b1 + c0 + j);
#pragma unroll
        for (int i = 0; i < 4; i++)
#pragma unroll
            for (int j = 0; j < 8; j++) acc[i][j] = bb[j];
    }
    for (int k = 0; k < CIN; k++) {
        float w[8], g[4];
        float4 w0 = *(const float4*)(W1s + k * 128 + c0);
        float4 w1 = *(const float4*)(W1s + k * 128 + c0 + 4);
        w[0] = w0.x; w[1] = w0.y; w[2] = w0.z; w[3] = w0.w;
        w[4] = w1.x; w[5] = w1.y; w[6] = w1.z; w[7] = w1.w;
#pragma unroll
        for (int i = 0; i < 4; i++) g[i] = Gs[(r0 + i) * 68 + k];
#pragma unroll
        for (int i = 0; i < 4; i++)
#pragma unroll
            for (int j = 0; j < 8; j++) acc[i][j] += g[i] * w[j];
    }
#pragma unroll
    for (int i = 0; i < 4; i++) {
        float4 v0, v1;
        v0.x = fmaxf(acc[i][0], 0.f); v0.y = fmaxf(acc[i][1], 0.f);
        v0.z = fmaxf(acc[i][2], 0.f); v0.w = fmaxf(acc[i][3], 0.f);
        v1.x = fmaxf(acc[i][4], 0.f); v1.y = fmaxf(acc[i][5], 0.f);
        v1.z = fmaxf(acc[i][6], 0.f); v1.w = fmaxf(acc[i][7], 0.f);
        *(float4*)(Hs + (r0 + i) * 132 + c0) = v0;
        *(float4*)(Hs + (r0 + i) * 132 + c0 + 4) = v1;
    }
    BAR_MLP();

    {
        float bb[8];
#pragma unroll
        for (int j = 0; j < 8; j++) bb[j] = __ldg(b2 + c0 + j);
#pragma unroll
        for (int i = 0; i < 4; i++)
#pragma unroll
            for (int j = 0; j < 8; j++) acc[i][j] = bb[j];
    }
    for (int k = 0; k < OUTDIM; k++) {
        float w[8], h[4];
        float4 w0 = *(const float4*)(W2s + k * 128 + c0);
        float4 w1 = *(const float4*)(W2s + k * 128 + c0 + 4);
        w[0] = w0.x; w[1] = w0.y; w[2] = w0.z; w[3] = w0.w;
        w[4] = w1.x; w[5] = w1.y; w[6] = w1.z; w[7] = w1.w;
#pragma unroll
        for (int i = 0; i < 4; i++) h[i] = Hs[(r0 + i) * 132 + k];
#pragma unroll
        for (int i = 0; i < 4; i++)
#pragma unroll
            for (int j = 0; j < 8; j++) acc[i][j] += h[i] * w[j];
    }
    // pool over this thread's 4 rows (within one query)
    {
        float m[8];
#pragma unroll
        for (int j = 0; j < 8; j++) {
            float v = acc[0][j];
#pragma unroll
            for (int i = 1; i < 4; i++) v = fmaxf(v, acc[i][j]);
            m[j] = v;
        }
        float4 v0, v1;
        v0.x = m[0]; v0.y = m[1]; v0.z = m[2]; v0.w = m[3];
        v1.x = m[4]; v1.y = m[5]; v1.z = m[6]; v1.w = m[7];
        *(float4*)(Ps + ty * 128 + c0) = v0;
        *(float4*)(Ps + ty * 128 + c0 + 4) = v1;
    }
    BAR_MLP();
    for (int e = t; e < 1024; e += 512) {
        int q = e >> 7, c = e & 127;
        Qs[e] = fmaxf(fmaxf(Ps[(4 * q + 0) * 128 + c], Ps[(4 * q + 1) * 128 + c]),
                      fmaxf(Ps[(4 * q + 2) * 128 + c], Ps[(4 * q + 3) * 128 + c]));
    }
    BAR_MLP();

    if (t < 256) {
        int w = t >> 5, l = t & 31;
        float4 v = *(const float4*)(Qs + w * 128 + l * 4);
        float sum = v.x + v.y + v.z + v.w;
        float sq = fmaf(v.x, v.x, fmaf(v.y, v.y, fmaf(v.z, v.z, v.w * v.w)));
#pragma unroll
        for (int off = 16; off; off >>= 1) {
            sum += __shfl_xor_sync(0xffffffffu, sum, off);
            sq += __shfl_xor_sync(0xffffffffu, sq, off);
        }
        float mu = sum * (1.0f / 128.0f);
        float var = sq * (1.0f / 128.0f) - mu * mu;
        float rs = rsqrtf(var + 1e-5f);
        int qg = q0 + w;
        int c = l * 4;
        float4 o;
        o.x = (v.x - mu) * rs * __ldg(lg + c + 0) + __ldg(lb + c + 0);
        o.y = (v.y - mu) * rs * __ldg(lg + c + 1) + __ldg(lb + c + 1);
        o.z = (v.z - mu) * rs * __ldg(lg + c + 2) + __ldg(lb + c + 2);
        o.w = (v.w - mu) * rs * __ldg(lg + c + 3) + __ldg(lb + c + 3);
        *(float4*)(outf + (((size_t)b * NSAMP + qg) << 7) + c) = o;
    }
    BAR_MLP();
}

__device__ void load_weights(float* sm, const float* __restrict__ W1,
                             const float* __restrict__ W2, int t) {
    for (int e = t; e < CIN * OUTDIM; e += 1024) {
        int sr = e >> 7, c = e & 127;
        int dr = (sr < 3) ? (64 + sr) : (sr - 3);
        sm[dr * 128 + c] = W1[e];
    }
    const float4* src = (const float4*)W2;
    float4* dst = (float4*)(sm + OFF_W2);
    for (int e = t; e < 4096; e += 1024) dst[e] = src[e];
}

// ============================================================================
// Fused persistent kernel with ready-queue scheduler.
// ============================================================================
__global__ __launch_bounds__(1024, 1)
void fused_kernel(const float* __restrict__ xyz, const float* __restrict__ feat,
                  const float* __restrict__ W1, const float* __restrict__ b1,
                  const float* __restrict__ W2, const float* __restrict__ b2,
                  const float* __restrict__ lg, const float* __restrict__ lb,
                  float* __restrict__ oxyz, float* __restrict__ ofeat) {
    extern __shared__ float sm[];
    __shared__ int shA, shQ0, shB;
    const int t = threadIdx.x;
    const int bid = blockIdx.x;

    int pendChunk = -1, pendB = 0, pendNeed = 0;

    if (bid < BATCH) {
        fps_part(sm, xyz, oxyz, bid, t);
        __syncthreads();
        load_weights(sm, W1, W2, t);
        __syncthreads();
    } else {
        int w = bid - BATCH;
        if (w < 128) {
            pendChunk = w >> 2;
            pendB = w & 3;
            pendNeed = (pendChunk + 1) * 64;
        }
        load_weights(sm, W1, W2, t);
        __syncthreads();
    }

    while (true) {
        __syncthreads();
        if (t == 0) {
            int a, q0 = 0, bb = 0;
            bool hasPend = (pendChunk >= 0);
            while (true) {
                if (hasPend && g_progress[pendB * 32] >= pendNeed) { a = 1; break; }
                if (hasPend) {
                    int cur = g_mlpTake;
                    if (cur < g_mlpAvail && cur < 1024) {
                        if (atomicCAS(&g_mlpTake, cur, cur + 1) == cur) {
                            __threadfence();
                            int m = g_mlpQueue[cur];
                            a = 2; q0 = (m >> 5) * 64 + (m & 7) * 8; bb = (m >> 3) & 3;
                            break;
                        }
                    } else {
                        __nanosleep(1000);
                    }
                } else {
                    int tk = atomicAdd(&g_mlpTake, 1);
                    if (tk >= 1024) { a = 0; break; }
                    while (g_mlpAvail <= tk) __nanosleep(500);
                    __threadfence();
                    int m = g_mlpQueue[tk];
                    a = 2; q0 = (m >> 5) * 64 + (m & 7) * 8; bb = (m >> 3) & 3;
                    break;
                }
            }
            shA = a; shQ0 = q0; shB = bb;
        }
        __syncthreads();
        int a = shA;
        if (a == 0) break;

        if (a == 1) {
            knn_chunk(sm + OFF_DYN, xyz, oxyz, pendB, pendChunk * 64, t);
            __syncthreads();
            if (t == 0) {
                int fi = pendChunk * 4 + pendB;
                int pos = atomicAdd(&g_mlpEnq, 8);
#pragma unroll
                for (int j = 0; j < 8; j++) g_mlpQueue[pos + j] = fi * 8 + j;
                __threadfence();
                while (g_mlpAvail != pos) __nanosleep(100);
                g_mlpAvail = pos + 8;
            }
            pendChunk = -1;
        } else {
            mlp_tile(sm, xyz, feat, oxyz, b1, b2, lg, lb, ofeat, shB, shQ0, t);
        }
    }
}

// ============================================================================
extern "C" void kernel_launch(void* const* d_in, const int* in_sizes, int n_in,
                              void* d_out, int out_size) {
    const float* xyz  = (const float*)d_in[0];
    const float* feat = (const float*)d_in[1];
    const float* W1   = (const float*)d_in[2];
    const float* b1   = (const float*)d_in[3];
    const float* W2   = (const float*)d_in[4];
    const float* b2   = (const float*)d_in[5];
    const float* lg   = (const float*)d_in[6];
    const float* lb   = (const float*)d_in[7];

    float* out = (float*)d_out;
    float* oxyz = out;                                  // (B, S, 3)
    float* ofeat = out + (size_t)BATCH * NSAMP * 3;     // (B, S, 128)

    cudaFuncSetAttribute(fused_kernel, cudaFuncAttributeMaxDynamicSharedMemorySize, DYN_BYTES);

    init_kernel<<<1, 1>>>();
    fused_kernel<<<148, 1024, DYN_BYTES>>>(xyz, feat, W1, b1, W2, b2, lg, lb, oxyz, ofeat);
}

// round 15
// speedup vs baseline: 1.3719x; 1.0403x over previous
#include <cuda_runtime.h>
#include <cuda_bf16.h>
#include <cstdint>

#define BATCH 4
#define NPTS 8192
#define NSAMP 2048
#define KNN_K 16
#define INDIM 64
#define OUTDIM 128
#define CIN 67

typedef unsigned long long ull;

// ---------------- global coordination state (128B-padded hot words) ----------------
__device__ int g_knn[BATCH * NSAMP * KNN_K];
__device__ volatile int g_progress[BATCH * 32];
__device__ __align__(128) int g_mlpEnq;
__device__ __align__(128) volatile int g_mlpAvail;
__device__ __align__(128) int g_mlpTake;
__device__ __align__(128) int g_mlpQueue[1024];

__global__ void init_kernel() {
    g_mlpEnq = 0;
    g_mlpAvail = 0;
    g_mlpTake = 0;
#pragma unroll
    for (int i = 0; i < BATCH; i++) g_progress[i * 32] = 0;
}

// ---- packed f32x2 helpers (per-lane bit-identical to scalar ops) ----
__device__ __forceinline__ ull f2pk(float lo, float hi) {
    ull r; asm("mov.b64 %0, {%1,%2};" : "=l"(r) : "f"(lo), "f"(hi)); return r;
}
__device__ __forceinline__ void f2up(ull v, float& lo, float& hi) {
    asm("mov.b64 {%0,%1}, %2;" : "=f"(lo), "=f"(hi) : "l"(v));
}
__device__ __forceinline__ ull f2add(ull a, ull b) {
    ull r; asm("add.rn.f32x2 %0, %1, %2;" : "=l"(r) : "l"(a), "l"(b)); return r;
}
__device__ __forceinline__ ull f2mul(ull a, ull b) {
    ull r; asm("mul.rn.f32x2 %0, %1, %2;" : "=l"(r) : "l"(a), "l"(b)); return r;
}
__device__ __forceinline__ ull f2fma(ull a, ull b, ull c) {
    ull r; asm("fma.rn.f32x2 %0, %1, %2, %3;" : "=l"(r) : "l"(a), "l"(b), "l"(c)); return r;
}

__device__ __forceinline__ int spread3(int v) {
    return (v & 1) | ((v & 2) << 2) | ((v & 4) << 4);
}

// ============================================================================
// Kernel A: FPS only (small code body). Grid BATCH x 1024 threads.
// Byte-identical to the proven R8/R10 FPS body + padded progress stores.
// ============================================================================
#define FPS_SMEM ((3 * NPTS + NPTS + NPTS + 1024 + 128 + 204 + 8) * 4)

__global__ __launch_bounds__(1024, 1)
void fps_kernel(const float* __restrict__ xyz, float* __restrict__ oxyz) {
    extern __shared__ float sm[];
    float* sxs = sm;
    float* sys = sxs + NPTS;
    float* szs = sys + NPTS;
    int* sorig = (int*)(szs + NPTS);
    int* spay  = sorig + NPTS;
    int* cellCnt = spay + NPTS;
    int* cellStart = cellCnt + 512;
    unsigned* pv = (unsigned*)(cellStart + 512);
    unsigned* pp = pv + 64;
    float* wred = (float*)(pp + 64);
    int* gpos0 = (int*)(wred + 198);

    const int b = blockIdx.x;
    const int t = threadIdx.x;
    const int wid = t >> 5;
    const int lane = t & 31;
    const float* bx = xyz + (size_t)b * NPTS * 3;

    {
        float lx = 3.4e38f, ly = 3.4e38f, lz = 3.4e38f;
        float hx = -3.4e38f, hy = -3.4e38f, hz = -3.4e38f;
        for (int i = t; i < NPTS; i += 1024) {
            float x = bx[3 * i], y = bx[3 * i + 1], z = bx[3 * i + 2];
            lx = fminf(lx, x); hx = fmaxf(hx, x);
            ly = fminf(ly, y); hy = fmaxf(hy, y);
            lz = fminf(lz, z); hz = fmaxf(hz, z);
        }
#pragma unroll
        for (int off = 16; off; off >>= 1) {
            lx = fminf(lx, __shfl_xor_sync(~0u, lx, off));
            ly = fminf(ly, __shfl_xor_sync(~0u, ly, off));
            lz = fminf(lz, __shfl_xor_sync(~0u, lz, off));
            hx = fmaxf(hx, __shfl_xor_sync(~0u, hx, off));
            hy = fmaxf(hy, __shfl_xor_sync(~0u, hy, off));
            hz = fmaxf(hz, __shfl_xor_sync(~0u, hz, off));
        }
        if (lane == 0) {
            wred[wid * 6 + 0] = lx; wred[wid * 6 + 1] = ly; wred[wid * 6 + 2] = lz;
            wred[wid * 6 + 3] = hx; wred[wid * 6 + 4] = hy; wred[wid * 6 + 5] = hz;
        }
        if (t < 512) cellCnt[t] = 0;
    }
    __syncthreads();
    if (t == 0) {
        float lx = wred[0], ly = wred[1], lz = wred[2];
        float hx = wred[3], hy = wred[4], hz = wred[5];
        for (int w = 1; w < 32; w++) {
            lx = fminf(lx, wred[w * 6 + 0]); ly = fminf(ly, wred[w * 6 + 1]);
            lz = fminf(lz, wred[w * 6 + 2]);
            hx = fmaxf(hx, wred[w * 6 + 3]); hy = fmaxf(hy, wred[w * 6 + 4]);
            hz = fmaxf(hz, wred[w * 6 + 5]);
        }
        wred[192] = lx; wred[193] = ly; wred[194] = lz;
        wred[195] = (hx > lx) ? 7.9999f / (hx - lx) : 0.0f;
        wred[196] = (hy > ly) ? 7.9999f / (hy - ly) : 0.0f;
        wred[197] = (hz > lz) ? 7.9999f / (hz - lz) : 0.0f;
    }
    __syncthreads();
    const float lox = wred[192], loy = wred[193], loz = wred[194];
    const float scx = wred[195], scy = wred[196], scz = wred[197];
    for (int i = t; i < NPTS; i += 1024) {
        float x = bx[3 * i], y = bx[3 * i + 1], z = bx[3 * i + 2];
        int qx = (int)((x - lox) * scx); qx = qx < 0 ? 0 : (qx > 7 ? 7 : qx);
        int qy = (int)((y - loy) * scy); qy = qy < 0 ? 0 : (qy > 7 ? 7 : qy);
        int qz = (int)((z - loz) * scz); qz = qz < 0 ? 0 : (qz > 7 ? 7 : qz);
        int ci = (spread3(qx) << 2) | (spread3(qy) << 1) | spread3(qz);
        atomicAdd(&cellCnt[ci], 1);
    }
    __syncthreads();
    if (t < 32) {
        int base = t * 16;
        int loc[16]; int run = 0;
#pragma unroll
        for (int k = 0; k < 16; k++) { loc[k] = run; run += cellCnt[base + k]; }
        int inc = run;
#pragma unroll
        for (int off = 1; off < 32; off <<= 1) {
            int v = __shfl_up_sync(~0u, inc, off);
            if (lane >= off) inc += v;
        }
        int excl = inc - run;
#pragma unroll
        for (int k = 0; k < 16; k++) cellStart[base + k] = excl + loc[k];
    }
    __syncthreads();
    if (t < 512) cellCnt[t] = 0;
    __syncthreads();
    for (int i = t; i < NPTS; i += 1024) {
        float x = bx[3 * i], y = bx[3 * i + 1], z = bx[3 * i + 2];
        int qx = (int)((x - lox) * scx); qx = qx < 0 ? 0 : (qx > 7 ? 7 : qx);
        int qy = (int)((y - loy) * scy); qy = qy < 0 ? 0 : (qy > 7 ? 7 : qy);
        int qz = (int)((z - loz) * scz); qz = qz < 0 ? 0 : (qz > 7 ? 7 : qz);
        int ci = (spread3(qx) << 2) | (spread3(qy) << 1) | spread3(qz);
        int p = cellStart[ci] + atomicAdd(&cellCnt[ci], 1);
        sxs[p] = x; sys[p] = y; szs[p] = z;
        sorig[p] = i;
        spay[p] = (i << 13) | p;
        if (i == 0) *gpos0 = p;
    }
    __syncthreads();

    const int base = t * 8;
    ull px2[4], py2[4], pz2[4];
    float pd[8];
    float blx = 3.4e38f, bly = 3.4e38f, blz = 3.4e38f;
    float bhx = -3.4e38f, bhy = -3.4e38f, bhz = -3.4e38f;
#pragma unroll
    for (int m = 0; m < 4; m++) {
        int p0 = base + 2 * m, p1 = p0 + 1;
        float x0 = sxs[p0], y0 = sys[p0], z0 = szs[p0];
        float x1 = sxs[p1], y1 = sys[p1], z1 = szs[p1];
        px2[m] = f2pk(x0, x1); py2[m] = f2pk(y0, y1); pz2[m] = f2pk(z0, z1);
        pd[2 * m] = 1e10f; pd[2 * m + 1] = 1e10f;
        blx = fminf(blx, fminf(x0, x1)); bhx = fmaxf(bhx, fmaxf(x0, x1));
        bly = fminf(bly, fminf(y0, y1)); bhy = fmaxf(bhy, fmaxf(y0, y1));
        blz = fminf(blz, fminf(z0, z1)); bhz = fmaxf(bhz, fmaxf(z0, z1));
    }
    float hvv = 1e10f;
    int hpp;
    {
        int p = 0x7fffffff;
#pragma unroll
        for (int i = 0; i < 8; i++) p = min(p, spay[base + i]);
        hpp = p;
    }
    __syncthreads();

    float cx, cy, cz;
    {
        int p0 = *gpos0;
        cx = sxs[p0]; cy = sys[p0]; cz = szs[p0];
        if (t == 0) {
            float* o = oxyz + (size_t)b * NSAMP * 3;
            o[0] = cx; o[1] = cy; o[2] = cz;
        }
    }

    int par = 0;
    for (int s = 1; s < NSAMP; s++) {
        const float mcx = -cx, mcy = -cy, mcz = -cz;
        float tx = fmaxf(fmaxf(__fadd_rn(blx, mcx), __fadd_rn(cx, -bhx)), 0.0f);
        float ty = fmaxf(fmaxf(__fadd_rn(bly, mcy), __fadd_rn(cy, -bhy)), 0.0f);
        float tz = fmaxf(fmaxf(__fadd_rn(blz, mcz), __fadd_rn(cz, -bhz)), 0.0f);
        float bnd = __fmul_rn(tx, tx);
        bnd = __fmaf_rn(ty, ty, bnd);
        bnd = __fmaf_rn(tz, tz, bnd);
        bool need = bnd < hvv;
        if (__any_sync(0xffffffffu, need)) {
            const ull ncx = f2pk(mcx, mcx);
            const ull ncy = f2pk(mcy, mcy);
            const ull ncz = f2pk(mcz, mcz);
#pragma unroll
            for (int m = 0; m < 4; m++) {
                ull dx = f2add(px2[m], ncx);
                ull dd = f2mul(dx, dx);
                ull dy = f2add(py2[m], ncy);
                dd = f2fma(dy, dy, dd);
                ull dz = f2add(pz2[m], ncz);
                dd = f2fma(dz, dz, dd);
                float d0, d1;
                f2up(dd, d0, d1);
                pd[2 * m] = fminf(pd[2 * m], d0);
                pd[2 * m + 1] = fminf(pd[2 * m + 1], d1);
            }
            float mv = pd[0];
#pragma unroll
            for (int i = 1; i < 8; i++) mv = fmaxf(mv, pd[i]);
            int p = 0x7fffffff;
#pragma unroll
            for (int i = 0; i < 8; i++)
                p = min(p, (pd[i] == mv) ? spay[base + i] : 0x7fffffff);
            hvv = mv; hpp = p;
        }
        unsigned bmaxv = __float_as_uint(hvv);
        unsigned wv = __reduce_max_sync(0xffffffffu, bmaxv);
        unsigned wp = __reduce_min_sync(0xffffffffu,
                                        (bmaxv == wv) ? (unsigned)hpp : 0x7fffffffu);
        if (lane == 0) { pv[par * 32 + wid] = wv; pp[par * 32 + wid] = wp; }
        __syncthreads();
        unsigned v3 = pv[par * 32 + lane];
        unsigned p3 = pp[par * 32 + lane];
        unsigned gv = __reduce_max_sync(0xffffffffu, v3);
        unsigned gp = __reduce_min_sync(0xffffffffu, (v3 == gv) ? p3 : 0x7fffffffu);
        int pos = (int)(gp & 0x1fffu);
        cx = sxs[pos]; cy = sys[pos]; cz = szs[pos];
        if (t == 0) {
            float* o = oxyz + ((size_t)b * NSAMP + s) * 3;
            o[0] = cx; o[1] = cy; o[2] = cz;
            if ((s & 31) == 31) {
                __threadfence();
                g_progress[b * 32] = s + 1;
            }
        }
        par ^= 1;
    }
    if (t == 0) { __threadfence(); g_progress[b * 32] = NSAMP; }
}

// ============================================================================
// Kernel B: worker (scheduler + KNN + MLP). Grid 144 x 256 threads.
// All 256 threads participate; plain __syncthreads throughout.
// smem: W1s 8576 | W2s 16384 | dyn 28672  = 53632 floats = 214528 B.
// ============================================================================
#define W_OFF_W2 8576
#define W_OFF_DYN 24960
#define W_DYN_FLOATS (W_OFF_DYN + 28672)
#define W_DYN_BYTES (W_DYN_FLOATS * 4)
#define KTS 1024

__device__ void knn_chunk(float* dyn, const float* __restrict__ xyz,
                          const float* __restrict__ qxyz, int b, int q0, int t) {
    float* stx = dyn;
    float* sty = dyn + 1024;
    float* stz = dyn + 2048;
    float* st2 = dyn + 3072;
    float* smd = dyn + 4096;
    int*   smi = (int*)(dyn + 7168);

    const int ql = t >> 2;
    const int par = t & 3;
    const int q = q0 + ql;

    const float* qp = qxyz + ((size_t)b * NSAMP + q) * 3;
    const float qx = qp[0], qy = qp[1], qz = qp[2];
    const float q2 = qx * qx + qy * qy + qz * qz;

    float dk[16];
    int ik[16];
#pragma unroll
    for (int i = 0; i < 16; i++) { dk[i] = 3.4e38f; ik[i] = 0; }

    const float* bx = xyz + (size_t)b * NPTS * 3;
    for (int tile = 0; tile < NPTS / KTS; tile++) {
        __syncthreads();
        for (int i = t; i < KTS; i += 256) {
            int p = tile * KTS + i;
            float x = bx[p * 3 + 0], y = bx[p * 3 + 1], z = bx[p * 3 + 2];
            stx[i] = x; sty[i] = y; stz[i] = z;
            st2[i] = x * x + y * y + z * z;
        }
        __syncthreads();
        for (int j = par; j < KTS; j += 4) {
            float dot = qx * stx[j] + qy * sty[j] + qz * stz[j];
            float d = q2 + st2[j] - 2.0f * dot;
            if (d < dk[0]) {
                int idx = tile * KTS + j;
                dk[0] = d; ik[0] = idx;
#pragma unroll
                for (int r = 0; r < 15; r++) {
                    if (dk[r] < dk[r + 1]) {
                        float td = dk[r]; dk[r] = dk[r + 1]; dk[r + 1] = td;
                        int ti = ik[r]; ik[r] = ik[r + 1]; ik[r + 1] = ti;
                    }
                }
            }
        }
    }
    __syncthreads();

    if (par) {
        int basee = ql * 48 + (par - 1) * 16;
#pragma unroll
        for (int i = 0; i < 16; i++) { smd[basee + i] = dk[i]; smi[basee + i] = ik[i]; }
    }
    __syncthreads();

    if (par == 0) {
        for (int e = 0; e < 48; e++) {
            float d = smd[ql * 48 + e];
            int idx = smi[ql * 48 + e];
            if (d < dk[0] || (d == dk[0] && idx < ik[0])) {
                dk[0] = d; ik[0] = idx;
#pragma unroll
                for (int r = 0; r < 15; r++) {
                    bool sw = (dk[r] < dk[r + 1]) ||
                              (dk[r] == dk[r + 1] && ik[r] < ik[r + 1]);
                    if (sw) {
                        float td = dk[r]; dk[r] = dk[r + 1]; dk[r + 1] = td;
                        int ti = ik[r]; ik[r] = ik[r + 1]; ik[r + 1] = ti;
                    }
                }
            }
        }
        int* dst = g_knn + (((size_t)b * NSAMP + q) << 4);
#pragma unroll
        for (int i = 0; i < 16; i++) dst[i] = ik[i];
    }
    __syncthreads();
}

// MLP tile: 8 queries, 256 threads, proven 8x8 register tile (R5 form).
__device__ void mlp_tile(float* sm, const float* __restrict__ xyz,
                         const float* __restrict__ feat,
                         const float* __restrict__ newxyz,
                         const float* __restrict__ b1, const float* __restrict__ b2,
                         const float* __restrict__ lg, const float* __restrict__ lb,
                         float* __restrict__ outf, int b, int q0, int t) {
    float* W1s = sm;
    float* W2s = sm + W_OFF_W2;
    float* dyn = sm + W_OFF_DYN;
    float* Gs  = dyn;               // 128 x 68  = 8704
    float* Hs  = dyn + 8704;        // 128 x 132 = 16896
    float* Ps  = dyn + 25600;       // 16 x 128  = 2048
    float* Qs  = dyn + 27648;       // 8 x 128   = 1024

    {
        int r = t >> 1, half = t & 1;
        int qlq = r >> 4, kk = r & 15;
        int q = q0 + qlq;
        int nidx = g_knn[(((size_t)b * NSAMP + q) << 4) + kk];
        const float* frow = feat + ((size_t)b * NPTS + nidx) * INDIM + half * 32;
        float* grow = Gs + r * 68;
#pragma unroll
        for (int i = 0; i < 8; i++) {
            float4 v = *(const float4*)(frow + i * 4);
            *(float4*)(grow + half * 32 + i * 4) = v;
        }
        if (half == 0) {
            const float* prow = xyz + ((size_t)b * NPTS + nidx) * 3;
            const float* crow = newxyz + ((size_t)b * NSAMP + q) * 3;
            grow[64] = prow[0] - crow[0];
            grow[65] = prow[1] - crow[1];
            grow[66] = prow[2] - crow[2];
        }
    }
    __syncthreads();

    const int tx = t & 15, ty = t >> 4;
    const int c0 = tx * 8, r0 = ty * 8;

    float acc[8][8];
    {
        float bb[8];
#pragma unroll
        for (int j = 0; j < 8; j++) bb[j] = __ldg(b1 + c0 + j);
#pragma unroll
        for (int i = 0; i < 8; i++)
#pragma unroll
            for (int j = 0; j < 8; j++) acc[i][j] = bb[j];
    }
    for (int k = 0; k < CIN; k++) {
        float w[8], g[8];
        float4 w0 = *(const float4*)(W1s + k * 128 + c0);
        float4 w1 = *(const float4*)(W1s + k * 128 + c0 + 4);
        w[0] = w0.x; w[1] = w0.y; w[2] = w0.z; w[3] = w0.w;
        w[4] = w1.x; w[5] = w1.y; w[6] = w1.z; w[7] = w1.w;
#pragma unroll
        for (int i = 0; i < 8; i++) g[i] = Gs[(r0 + i) * 68 + k];
#pragma unroll
        for (int i = 0; i < 8; i++)
#pragma unroll
            for (int j = 0; j < 8; j++) acc[i][j] += g[i] * w[j];
    }
#pragma unroll
    for (int i = 0; i < 8; i++) {
        float4 v0, v1;
        v0.x = fmaxf(acc[i][0], 0.f); v0.y = fmaxf(acc[i][1], 0.f);
        v0.z = fmaxf(acc[i][2], 0.f); v0.w = fmaxf(acc[i][3], 0.f);
        v1.x = fmaxf(acc[i][4], 0.f); v1.y = fmaxf(acc[i][5], 0.f);
        v1.z = fmaxf(acc[i][6], 0.f); v1.w = fmaxf(acc[i][7], 0.f);
        *(float4*)(Hs + (r0 + i) * 132 + c0) = v0;
        *(float4*)(Hs + (r0 + i) * 132 + c0 + 4) = v1;
    }
    __syncthreads();

    {
        float bb[8];
#pragma unroll
        for (int j = 0; j < 8; j++) bb[j] = __ldg(b2 + c0 + j);
#pragma unroll
        for (int i = 0; i < 8; i++)
#pragma unroll
            for (int j = 0; j < 8; j++) acc[i][j] = bb[j];
    }
    for (int k = 0; k < OUTDIM; k++) {
        float w[8], h[8];
        float4 w0 = *(const float4*)(W2s + k * 128 + c0);
        float4 w1 = *(const float4*)(W2s + k * 128 + c0 + 4);
        w[0] = w0.x; w[1] = w0.y; w[2] = w0.z; w[3] = w0.w;
        w[4] = w1.x; w[5] = w1.y; w[6] = w1.z; w[7] = w1.w;
#pragma unroll
        for (int i = 0; i < 8; i++) h[i] = Hs[(r0 + i) * 132 + k];
#pragma unroll
        for (int i = 0; i < 8; i++)
#pragma unroll
            for (int j = 0; j < 8; j++) acc[i][j] += h[i] * w[j];
    }
    {
        float m[8];
#pragma unroll
        for (int j = 0; j < 8; j++) {
            float v = acc[0][j];
#pragma unroll
            for (int i = 1; i < 8; i++) v = fmaxf(v, acc[i][j]);
            m[j] = v;
        }
        float4 v0, v1;
        v0.x = m[0]; v0.y = m[1]; v0.z = m[2]; v0.w = m[3];
        v1.x = m[4]; v1.y = m[5]; v1.z = m[6]; v1.w = m[7];
        *(float4*)(Ps + ty * 128 + c0) = v0;
        *(float4*)(Ps + ty * 128 + c0 + 4) = v1;
    }
    __syncthreads();
    for (int e = t; e < 1024; e += 256) {
        int q = e >> 7, c = e & 127;
        Qs[e] = fmaxf(Ps[(2 * q) * 128 + c], Ps[(2 * q + 1) * 128 + c]);
    }
    __syncthreads();

    {
        int w = t >> 5, l = t & 31;
        float4 v = *(const float4*)(Qs + w * 128 + l * 4);
        float sum = v.x + v.y + v.z + v.w;
        float sq = fmaf(v.x, v.x, fmaf(v.y, v.y, fmaf(v.z, v.z, v.w * v.w)));
#pragma unroll
        for (int off = 16; off; off >>= 1) {
            sum += __shfl_xor_sync(0xffffffffu, sum, off);
            sq += __shfl_xor_sync(0xffffffffu, sq, off);
        }
        float mu = sum * (1.0f / 128.0f);
        float var = sq * (1.0f / 128.0f) - mu * mu;
        float rs = rsqrtf(var + 1e-5f);
        int qg = q0 + w;
        int c = l * 4;
        float4 o;
        o.x = (v.x - mu) * rs * __ldg(lg + c + 0) + __ldg(lb + c + 0);
        o.y = (v.y - mu) * rs * __ldg(lg + c + 1) + __ldg(lb + c + 1);
        o.z = (v.z - mu) * rs * __ldg(lg + c + 2) + __ldg(lb + c + 2);
        o.w = (v.w - mu) * rs * __ldg(lg + c + 3) + __ldg(lb + c + 3);
        *(float4*)(outf + (((size_t)b * NSAMP + qg) << 7) + c) = o;
    }
    __syncthreads();
}

__global__ __launch_bounds__(256, 1)
void worker_kernel(const float* __restrict__ xyz, const float* __restrict__ feat,
                   const float* __restrict__ W1, const float* __restrict__ b1,
                   const float* __restrict__ W2, const float* __restrict__ b2,
                   const float* __restrict__ lg, const float* __restrict__ lb,
                   const float* __restrict__ oxyz, float* __restrict__ ofeat) {
    extern __shared__ float sm[];
    __shared__ int shA, shQ0, shB;
    const int t = threadIdx.x;
    const int w = blockIdx.x;            // 0..143

    int pendChunk = -1, pendB = 0, pendNeed = 0;
    if (w < 128) {
        pendChunk = w >> 2;              // 0..31
        pendB = w & 3;
        pendNeed = (pendChunk + 1) * 64;
    }

    // load weights once (W1 rows permuted to match G layout)
    for (int e = t; e < CIN * OUTDIM; e += 256) {
        int sr = e >> 7, c = e & 127;
        int dr = (sr < 3) ? (64 + sr) : (sr - 3);
        sm[dr * 128 + c] = W1[e];
    }
    {
        const float4* src = (const float4*)W2;
        float4* dst = (float4*)(sm + W_OFF_W2);
        for (int e = t; e < 4096; e += 256) dst[e] = src[e];
    }
    __syncthreads();

    while (true) {
        __syncthreads();
        if (t == 0) {
            int a, q0 = 0, bb = 0;
            bool hasPend = (pendChunk >= 0);
            while (true) {
                if (hasPend && g_progress[pendB * 32] >= pendNeed) { a = 1; break; }
                if (hasPend) {
                    int cur = g_mlpTake;
                    if (cur < g_mlpAvail && cur < 1024) {
                        if (atomicCAS(&g_mlpTake, cur, cur + 1) == cur) {
                            __threadfence();
                            int m = g_mlpQueue[cur];
                            a = 2; q0 = (m >> 5) * 64 + (m & 7) * 8; bb = (m >> 3) & 3;
                            break;
                        }
                    } else {
                        __nanosleep(500);
                    }
                } else {
                    int tk = atomicAdd(&g_mlpTake, 1);
                    if (tk >= 1024) { a = 0; break; }
                    while (g_mlpAvail <= tk) __nanosleep(500);
                    __threadfence();
                    int m = g_mlpQueue[tk];
                    a = 2; q0 = (m >> 5) * 64 + (m & 7) * 8; bb = (m >> 3) & 3;
                    break;
                }
            }
            shA = a; shQ0 = q0; shB = bb;
        }
        __syncthreads();
        int a = shA;
        if (a == 0) break;

        if (a == 1) {
            knn_chunk(sm + W_OFF_DYN, xyz, oxyz, pendB, pendChunk * 64, t);
            __syncthreads();
            if (t == 0) {
                int fi = pendChunk * 4 + pendB;
                int pos = atomicAdd(&g_mlpEnq, 8);
#pragma unroll
                for (int j = 0; j < 8; j++) g_mlpQueue[pos + j] = fi * 8 + j;
                __threadfence();
                while (g_mlpAvail != pos) __nanosleep(100);
                g_mlpAvail = pos + 8;
            }
            pendChunk = -1;
        } else {
            mlp_tile(sm, xyz, feat, oxyz, b1, b2, lg, lb, ofeat, shB, shQ0, t);
        }
    }
}

// ============================================================================
// Launch: fork-join graph — fps_kernel and worker_kernel run concurrently.
// ============================================================================
extern "C" void kernel_launch(void* const* d_in, const int* in_sizes, int n_in,
                              void* d_out, int out_size) {
    const float* xyz  = (const float*)d_in[0];
    const float* feat = (const float*)d_in[1];
    const float* W1   = (const float*)d_in[2];
    const float* b1   = (const float*)d_in[3];
    const float* W2   = (const float*)d_in[4];
    const float* b2   = (const float*)d_in[5];
    const float* lg   = (const float*)d_in[6];
    const float* lb   = (const float*)d_in[7];

    float* out = (float*)d_out;
    float* oxyz = out;                                  // (B, S, 3)
    float* ofeat = out + (size_t)BATCH * NSAMP * 3;     // (B, S, 128)

    cudaFuncSetAttribute(fps_kernel, cudaFuncAttributeMaxDynamicSharedMemorySize, FPS_SMEM);
    cudaFuncSetAttribute(worker_kernel, cudaFuncAttributeMaxDynamicSharedMemorySize, W_DYN_BYTES);

    cudaStream_t s2;
    cudaStreamCreateWithFlags(&s2, cudaStreamNonBlocking);
    cudaEvent_t e0, e1;
    cudaEventCreateWithFlags(&e0, cudaEventDisableTiming);
    cudaEventCreateWithFlags(&e1, cudaEventDisableTiming);

    init_kernel<<<1, 1>>>();
    cudaEventRecord(e0, 0);
    cudaStreamWaitEvent(s2, e0, 0);

    fps_kernel<<<BATCH, 1024, FPS_SMEM>>>(xyz, oxyz);
    worker_kernel<<<144, 256, W_DYN_BYTES, s2>>>(xyz, feat, W1, b1, W2, b2,
                                                 lg, lb, oxyz, ofeat);

    cudaEventRecord(e1, s2);
    cudaStreamWaitEvent(0, e1, 0);

    cudaEventDestroy(e0);
    cudaEventDestroy(e1);
    cudaStreamDestroy(s2);
}